// round 1
// baseline (speedup 1.0000x reference)
#include <cuda_runtime.h>
#include <cuda_bf16.h>

// ROI Align (torchvision semantics), aligned=False equivalent per reference:
//   scale = 0.25, OUT = 7, sampling RATIO = 2
//   features: (2, 256, 200, 304) fp32, boxes: (2, 512, 4) fp32
//   output:   (1024, 256, 7, 7) fp32
//
// One thread per output element. Linear index order (r, c, ph, pw) with pw
// fastest so consecutive threads touch adjacent x positions of the same
// channel row (NCHW) -> coalesced-ish gathers, heavy L1/L2 reuse.

#define NBATCH 2
#define NCH    256
#define FH     200
#define FW     304
#define KBOX   512          // boxes per batch
#define POUT   7
#define RATIO_ 2
#define SCALE_ 0.25f

__device__ __forceinline__ void axis_prep(float t, int size,
                                          int& lo, int& hi, float& frac,
                                          bool& valid)
{
    // reference _axis_prep semantics
    valid = (t > -1.0f) && (t < (float)size);
    float tc  = (t < 0.0f) ? 0.0f : t;
    float low = floorf(tc);
    if (low >= (float)(size - 1)) {
        lo = size - 1;
        hi = size - 1;
        frac = 0.0f;
    } else {
        lo = (int)low;
        hi = lo + 1;
        frac = tc - low;
    }
}

__global__ void __launch_bounds__(256)
roi_align_kernel(const float* __restrict__ feat,
                 const float* __restrict__ boxes,
                 float* __restrict__ out,
                 int total)
{
    int idx = blockIdx.x * blockDim.x + threadIdx.x;
    if (idx >= total) return;

    // decompose (r, c, ph, pw), pw fastest
    int pw = idx % POUT;
    int t  = idx / POUT;
    int ph = t % POUT;
    t /= POUT;
    int c  = t % NCH;
    int r  = t / NCH;

    int b = r >> 9;   // r / KBOX  (KBOX = 512)

    // box -> feature coords (whole block shares one ROI: broadcast loads)
    float x1 = __ldg(&boxes[r * 4 + 0]) * SCALE_;
    float y1 = __ldg(&boxes[r * 4 + 1]) * SCALE_;
    float x2 = __ldg(&boxes[r * 4 + 2]) * SCALE_;
    float y2 = __ldg(&boxes[r * 4 + 3]) * SCALE_;

    float roi_w = fmaxf(x2 - x1, 1.0f);
    float roi_h = fmaxf(y2 - y1, 1.0f);

    float bw = roi_w / (float)POUT;   // match reference: roi_w/OUT then *grid
    float bh = roi_h / (float)POUT;

    const float* __restrict__ fbase = feat + ((size_t)(b * NCH + c)) * (FH * FW);

    // Precompute the 2 x-axis preps for this pw (shared by both iy iterations)
    int   xl[RATIO_], xh[RATIO_];
    float fx[RATIO_];
    bool  vx[RATIO_];
#pragma unroll
    for (int ix = 0; ix < RATIO_; ix++) {
        int   s  = pw * RATIO_ + ix;
        float g  = ((float)s + 0.5f) * 0.5f;       // grid = (s+0.5)/RATIO
        float xs = x1 + g * bw;
        axis_prep(xs, FW, xl[ix], xh[ix], fx[ix], vx[ix]);
    }

    float sum = 0.0f;
#pragma unroll
    for (int iy = 0; iy < RATIO_; iy++) {
        int   s  = ph * RATIO_ + iy;
        float g  = ((float)s + 0.5f) * 0.5f;
        float ys = y1 + g * bh;
        int   yl, yh;
        float fy;
        bool  vy;
        axis_prep(ys, FH, yl, yh, fy, vy);

        const float* rowl = fbase + yl * FW;
        const float* rowh = fbase + yh * FW;
        float hy = 1.0f - fy;

#pragma unroll
        for (int ix = 0; ix < RATIO_; ix++) {
            if (vy && vx[ix]) {
                float v00 = __ldg(&rowl[xl[ix]]);
                float v01 = __ldg(&rowl[xh[ix]]);
                float v10 = __ldg(&rowh[xl[ix]]);
                float v11 = __ldg(&rowh[xh[ix]]);
                float hx = 1.0f - fx[ix];
                sum += hy * (hx * v00 + fx[ix] * v01)
                     + fy * (hx * v10 + fx[ix] * v11);
            }
        }
    }

    out[idx] = sum * 0.25f;   // mean over RATIO*RATIO sub-samples
}

extern "C" void kernel_launch(void* const* d_in, const int* in_sizes, int n_in,
                              void* d_out, int out_size)
{
    const float* feat  = (const float*)d_in[0];
    const float* boxes = (const float*)d_in[1];
    float* out = (float*)d_out;

    int total = out_size;                    // 1024*256*49 = 12,845,056
    int threads = 256;
    int blocks = (total + threads - 1) / threads;
    roi_align_kernel<<<blocks, threads>>>(feat, boxes, out, total);
}